// round 9
// baseline (speedup 1.0000x reference)
#include <cuda_runtime.h>
#include <cuda_bf16.h>

// Problem constants
#define BB 2
#define NN 8192
#define CC 64
#define DD 3
#define MM 2048   // NPOINT
#define SS 32     // NSAMPLE

// Output layout (concatenated tuple, row-major each):
//  group_xyz  (2,2048,32,3)      = 393216
//  group_fts  (2,128,3,2048,32)  = 50331648
//  new_xyz    (2,2048,3)         = 12288
//  new_fts    (2,128,3,2048,1)   = 1572864
#define OFF_GXYZ 0L
#define OFF_GFTS 393216L
#define OFF_NXYZ (393216L + 50331648L)
#define OFF_NFTS (393216L + 50331648L + 12288L)

__device__ int g_fps[BB * MM];
__device__ int g_nbrA[BB * MM * SS];   // v11: (qq-2dot)+pp  -> group_xyz (output 0, tolerant probe)
__device__ int g_nbrB[BB * MM * SS];   // v10: qq+(pp-2dot)  -> group_fts (output 1, exactness bet)

// strict (non-contracted) square-sum — matches XLA's fused square+reduce
// (proven bit-exact by FPS over 2047 compounding iterations)
__device__ __forceinline__ float sq3(float x, float y, float z) {
    return __fadd_rn(__fadd_rn(__fmul_rn(x, x), __fmul_rn(y, y)), __fmul_rn(z, z));
}

// ---------------------------------------------------------------------------
// 1) Furthest point sampling (frozen — bit-exact)
// ---------------------------------------------------------------------------
__global__ void __launch_bounds__(1024, 1) fps_kernel(const float* __restrict__ xyz) {
    const int b = blockIdx.x;
    const float* p = xyz + (long)b * NN * 3;
    const int tid = threadIdx.x;
    const int lane = tid & 31, warp = tid >> 5;

    float px[8], py[8], pz[8], md[8];
#pragma unroll
    for (int j = 0; j < 8; j++) {
        int i = tid + j * 1024;
        px[j] = p[3 * i + 0];
        py[j] = p[3 * i + 1];
        pz[j] = p[3 * i + 2];
        md[j] = 1e10f;
    }

    __shared__ float s_val[32];
    __shared__ int   s_idx[32];
    __shared__ int   s_best;

    if (tid == 0) g_fps[b * MM] = 0;

    float lx = p[0], ly = p[1], lz = p[2];

    for (int it = 1; it < MM; it++) {
        float bv = -1.0f;
        int bi = 0;
#pragma unroll
        for (int j = 0; j < 8; j++) {
            float dx = __fsub_rn(px[j], lx);
            float dy = __fsub_rn(py[j], ly);
            float dz = __fsub_rn(pz[j], lz);
            float d = sq3(dx, dy, dz);
            float m = fminf(md[j], d);
            md[j] = m;
            if (m > bv) { bv = m; bi = tid + j * 1024; }
        }
#pragma unroll
        for (int o = 16; o > 0; o >>= 1) {
            float ov = __shfl_down_sync(0xffffffffu, bv, o);
            int   oi = __shfl_down_sync(0xffffffffu, bi, o);
            if (ov > bv || (ov == bv && oi < bi)) { bv = ov; bi = oi; }
        }
        if (lane == 0) { s_val[warp] = bv; s_idx[warp] = bi; }
        __syncthreads();
        if (warp == 0) {
            bv = s_val[lane];
            bi = s_idx[lane];
#pragma unroll
            for (int o = 16; o > 0; o >>= 1) {
                float ov = __shfl_down_sync(0xffffffffu, bv, o);
                int   oi = __shfl_down_sync(0xffffffffu, bi, o);
                if (ov > bv || (ov == bv && oi < bi)) { bv = ov; bi = oi; }
            }
            if (lane == 0) {
                s_best = bi;
                g_fps[b * MM + it] = bi;
            }
        }
        __syncthreads();
        int last = s_best;
        lx = p[3 * last + 0];
        ly = p[3 * last + 1];
        lz = p[3 * last + 2];
    }
}

// ---------------------------------------------------------------------------
// 2) KNN, templated on combine association (dot fixed at fma-ascending).
//    VAR==0 (v10): d = qq + (pp - 2*dot)
//    VAR==1 (v11): d = (qq - 2*dot) + pp
//    qq/pp strict; ties: LOWER index first (stable).
// ---------------------------------------------------------------------------
template <int VAR>
__global__ void __launch_bounds__(256) knn_kernel(const float* __restrict__ xyz,
                                                  int* __restrict__ nbr_out) {
    const int m = blockIdx.x;
    const int b = blockIdx.y;
    const float* p = xyz + (long)b * NN * 3;
    const int t = threadIdx.x;

    const int qi = g_fps[b * MM + m];
    const float qx = p[3 * qi + 0], qy = p[3 * qi + 1], qz = p[3 * qi + 2];
    const float qq = sq3(qx, qy, qz);

    float d[32];
#pragma unroll
    for (int j = 0; j < 32; j++) {
        int i = j * 256 + t;
        float x = p[3 * i + 0], y = p[3 * i + 1], z = p[3 * i + 2];
        float pp = sq3(x, y, z);
        float dot = __fmaf_rn(qz, z, __fmaf_rn(qy, y, __fmul_rn(qx, x)));
        float two_dot = __fmul_rn(2.0f, dot);
        if (VAR == 0) {
            d[j] = __fadd_rn(qq, __fsub_rn(pp, two_dot));
        } else {
            d[j] = __fadd_rn(__fsub_rn(qq, two_dot), pp);
        }
    }

    unsigned excl = 0u;
    float mv = d[0];
    int mi = t;
#pragma unroll
    for (int j = 1; j < 32; j++) {
        int i = j * 256 + t;
        if (d[j] < mv) { mv = d[j]; mi = i; }  // strict < : lower idx wins ties
    }

    __shared__ float s_v[8];
    __shared__ int   s_i[8];
    __shared__ int   s_b;
    const int lane = t & 31, w = t >> 5;
    const int out_base = (b * MM + m) * SS;

    for (int s = 0; s < SS; s++) {
        float bv = mv;
        int bi = mi;
#pragma unroll
        for (int o = 16; o > 0; o >>= 1) {
            float ov = __shfl_down_sync(0xffffffffu, bv, o);
            int   oi = __shfl_down_sync(0xffffffffu, bi, o);
            if (ov < bv || (ov == bv && oi < bi)) { bv = ov; bi = oi; }
        }
        if (lane == 0) { s_v[w] = bv; s_i[w] = bi; }
        __syncthreads();
        if (t == 0) {
            bv = s_v[0]; bi = s_i[0];
#pragma unroll
            for (int k = 1; k < 8; k++) {
                float ov = s_v[k]; int oi = s_i[k];
                if (ov < bv || (ov == bv && oi < bi)) { bv = ov; bi = oi; }
            }
            s_b = bi;
            nbr_out[out_base + s] = bi;
        }
        __syncthreads();
        int win = s_b;
        if ((win & 255) == t) {
            excl |= 1u << (win >> 8);
            mv = 3.4e38f;
            mi = 0x7fffffff;
#pragma unroll
            for (int j = 0; j < 32; j++) {
                if (!(excl & (1u << j))) {
                    int i = j * 256 + t;
                    if (d[j] < mv) { mv = d[j]; mi = i; }
                }
            }
        }
    }
}

// ---------------------------------------------------------------------------
// 3) group_xyz + new_xyz   (variant-A indices: v11 probe, tolerant output)
// ---------------------------------------------------------------------------
__global__ void __launch_bounds__(256) gxyz_kernel(const float* __restrict__ xyz,
                                                   float* __restrict__ out) {
    int tid = blockIdx.x * 256 + threadIdx.x;  // over B*M*S = 131072
    if (tid >= BB * MM * SS) return;
    int s = tid & 31;
    int m = (tid >> 5) & (MM - 1);
    int b = tid >> 16;
    const float* p = xyz + (long)b * NN * 3;

    int i = g_nbrA[tid];
    float* o = out + OFF_GXYZ + (long)tid * 3;
    o[0] = p[3 * i + 0];
    o[1] = p[3 * i + 1];
    o[2] = p[3 * i + 2];

    if (s == 0) {
        int q = g_fps[b * MM + m];
        float* o2 = out + OFF_NXYZ + (long)(b * MM + m) * 3;
        o2[0] = p[3 * q + 0];
        o2[1] = p[3 * q + 1];
        o2[2] = p[3 * q + 2];
    }
}

// ---------------------------------------------------------------------------
// 4) group_fts + new_fts_out   (variant-B indices: v10, exactness bet)
// ---------------------------------------------------------------------------
__global__ void __launch_bounds__(256) gfts_kernel(const float* __restrict__ fts,
                                                   float* __restrict__ out) {
    __shared__ float row[NN];
    __shared__ float ctr[512];

    const int r = blockIdx.x;       // 0..383
    const int chunk = blockIdx.y;   // 0..3
    const int b = r / (CC * DD);
    const int cd = r % (CC * DD);
    const int c = cd / DD;
    const int dd = cd % DD;
    const int t = threadIdx.x;

    const float* src = fts + ((long)(b * CC + c) * DD + dd) * NN;
#pragma unroll
    for (int k = 0; k < 8; k++) {
        int i = (k * 256 + t) * 4;
        *(float4*)&row[i] = *(const float4*)&src[i];
    }
    __syncthreads();

    const int m0 = chunk * 512;
#pragma unroll
    for (int k = 0; k < 2; k++) {
        int ml = k * 256 + t;
        ctr[ml] = row[g_fps[b * MM + m0 + ml]];
    }
    __syncthreads();

    float* o1 = out + OFF_GFTS + ((long)(b * 2 * CC + c) * DD + dd) * MM * SS;
    float* o2 = o1 + (long)CC * DD * MM * SS;
    const int* nb = g_nbrB + (b * MM + m0) * SS;
    float* nfo1 = out + OFF_NFTS + ((long)(b * 2 * CC + c) * DD + dd) * MM + m0;
    float* nfo2 = nfo1 + (long)CC * DD * MM;

    for (int e = t; e < 512 * 8; e += 256) {
        int ml = e >> 3;
        int s4 = e & 7;
        int m = m0 + ml;
        int4 idx = *(const int4*)&nb[ml * SS + s4 * 4];
        float cv = ctr[ml];
        float4 v;
        v.x = __fsub_rn(row[idx.x], cv);
        v.y = __fsub_rn(row[idx.y], cv);
        v.z = __fsub_rn(row[idx.z], cv);
        v.w = __fsub_rn(row[idx.w], cv);
        long oo = (long)m * SS + s4 * 4;
        *(float4*)&o1[oo] = v;
        float4 cc4 = {cv, cv, cv, cv};
        *(float4*)&o2[oo] = cc4;
        if (s4 == 0) {
            nfo1[ml] = v.x;
            nfo2[ml] = cv;
        }
    }
}

// ---------------------------------------------------------------------------
extern "C" void kernel_launch(void* const* d_in, const int* in_sizes, int n_in,
                              void* d_out, int out_size) {
    const float* xyz = (const float*)d_in[0];
    const float* fts = (const float*)d_in[1];
    if (n_in >= 2 && in_sizes[0] != BB * NN * 3) {
        const float* tmp = xyz; xyz = fts; fts = tmp;
    }
    float* out = (float*)d_out;

    int* nbrA;  cudaGetSymbolAddress((void**)&nbrA, g_nbrA);
    int* nbrB;  cudaGetSymbolAddress((void**)&nbrB, g_nbrB);

    fps_kernel<<<BB, 1024>>>(xyz);

    dim3 kg(MM, BB);
    knn_kernel<1><<<kg, 256>>>(xyz, nbrA);   // v11 -> output 0 (probe)
    knn_kernel<0><<<kg, 256>>>(xyz, nbrB);   // v10 -> output 1 (bet)

    gxyz_kernel<<<(BB * MM * SS + 255) / 256, 256>>>(xyz, out);

    dim3 gg(BB * CC * DD, 4);
    gfts_kernel<<<gg, 256>>>(fts, out);
}

// round 10
// speedup vs baseline: 1.8434x; 1.8434x over previous
#include <cuda_runtime.h>
#include <cuda_bf16.h>

// Problem constants
#define BB 2
#define NN 8192
#define CC 64
#define DD 3
#define MM 2048   // NPOINT
#define SS 32     // NSAMPLE

// Output layout (concatenated tuple, row-major each)
#define OFF_GXYZ 0L
#define OFF_GFTS 393216L
#define OFF_NXYZ (393216L + 50331648L)
#define OFF_NFTS (393216L + 50331648L + 12288L)

__device__ int g_fps[BB * MM];
__device__ int g_nbr[BB * MM * SS];

// packed f32x2 helpers (lane-wise IEEE rn — bit-identical to scalar)
#define MUL_F32X2(out, a, b) \
    asm("mul.rn.f32x2 %0, %1, %2;" : "=l"(out) : "l"(a), "l"(b))
#define ADD_F32X2(out, a, b) \
    asm("add.rn.f32x2 %0, %1, %2;" : "=l"(out) : "l"(a), "l"(b))
#define PACK_F32X2(out, lo, hi) \
    asm("mov.b64 %0, {%1, %2};" : "=l"(out) : "f"(lo), "f"(hi))
#define UNPACK_F32X2(lo, hi, in) \
    asm("mov.b64 {%0, %1}, %2;" : "=f"(lo), "=f"(hi) : "l"(in))

// strict (non-contracted) square-sum — matches reference fused square+reduce
__device__ __forceinline__ float sq3(float x, float y, float z) {
    return __fadd_rn(__fadd_rn(__fmul_rn(x, x), __fmul_rn(y, y)), __fmul_rn(z, z));
}

// ---------------------------------------------------------------------------
// 1) FPS: one block/batch, 256 threads x 32 pts. Packed-f32x2 distances,
//    value-only min/max inner loop, post-hoc index recovery via atomicMin.
//    Arithmetic bit-identical to reference: dx=x+(-lx); ((dx²+dy²)+dz²);
//    argmax = first (lowest) index achieving the max.
// ---------------------------------------------------------------------------
__global__ void __launch_bounds__(256, 1) fps_kernel(const float* __restrict__ xyz) {
    const int b = blockIdx.x;
    const float* p = xyz + (long)b * NN * 3;
    const int tid = threadIdx.x;
    const int lane = tid & 31, warp = tid >> 5;

    // point i = j*256 + tid, j in [0,32); pairs (2k, 2k+1)
    unsigned long long px2[16], py2[16], pz2[16];
    float md[32];
#pragma unroll
    for (int k = 0; k < 16; k++) {
        int i0 = (2 * k) * 256 + tid;
        int i1 = (2 * k + 1) * 256 + tid;
        PACK_F32X2(px2[k], p[3 * i0 + 0], p[3 * i1 + 0]);
        PACK_F32X2(py2[k], p[3 * i0 + 1], p[3 * i1 + 1]);
        PACK_F32X2(pz2[k], p[3 * i0 + 2], p[3 * i1 + 2]);
        md[2 * k] = 1e10f;
        md[2 * k + 1] = 1e10f;
    }

    __shared__ float s_val[8];
    __shared__ int   s_best[2];

    if (tid == 0) {
        g_fps[b * MM] = 0;
        s_best[0] = 0x7fffffff;
        s_best[1] = 0x7fffffff;
    }
    __syncthreads();

    float lx = p[0], ly = p[1], lz = p[2];

    for (int it = 1; it < MM; it++) {
        unsigned long long nlx2, nly2, nlz2;
        float nlx = -lx, nly = -ly, nlz = -lz;
        PACK_F32X2(nlx2, nlx, nlx);
        PACK_F32X2(nly2, nly, nly);
        PACK_F32X2(nlz2, nlz, nlz);

        float bv = -1.0f;
#pragma unroll
        for (int k = 0; k < 16; k++) {
            unsigned long long dx2, dy2, dz2, xx, yy, ss, zz, dd;
            ADD_F32X2(dx2, px2[k], nlx2);           // x - lx  (== x + (-lx))
            ADD_F32X2(dy2, py2[k], nly2);
            ADD_F32X2(dz2, pz2[k], nlz2);
            MUL_F32X2(xx, dx2, dx2);
            MUL_F32X2(yy, dy2, dy2);
            ADD_F32X2(ss, xx, yy);                  // (dx² + dy²)
            MUL_F32X2(zz, dz2, dz2);
            ADD_F32X2(dd, ss, zz);                  // + dz²
            float dlo, dhi;
            UNPACK_F32X2(dlo, dhi, dd);
            float m0 = fminf(md[2 * k], dlo);
            float m1 = fminf(md[2 * k + 1], dhi);
            md[2 * k] = m0;
            md[2 * k + 1] = m1;
            bv = fmaxf(bv, m0);
            bv = fmaxf(bv, m1);
        }

        // warp butterfly max (all lanes get warp max)
        float wv = bv;
#pragma unroll
        for (int o = 16; o > 0; o >>= 1)
            wv = fmaxf(wv, __shfl_xor_sync(0xffffffffu, wv, o));
        if (lane == 0) s_val[warp] = wv;
        __syncthreads();                            // bar A: s_val + next-slot reset visible

        float blockv = s_val[0];
#pragma unroll
        for (int k = 1; k < 8; k++) blockv = fmaxf(blockv, s_val[k]);

        const int slot = it & 1;
        if (bv == blockv) {
            // descending scan keeps the LOWEST matching index (first-max)
            int my = 0x7fffffff;
#pragma unroll
            for (int j = 31; j >= 0; j--)
                if (md[j] == blockv) my = j * 256 + tid;
            atomicMin(&s_best[slot], my);
        }
        if (tid == 0) s_best[slot ^ 1] = 0x7fffffff;   // reset next slot (safe between bars)
        __syncthreads();                            // bar B: atomicMin complete

        int last = s_best[slot];
        if (tid == 0) g_fps[b * MM + it] = last;
        lx = p[3 * last + 0];                       // L1 broadcast
        ly = p[3 * last + 1];
        lz = p[3 * last + 2];
    }
}

// ---------------------------------------------------------------------------
// 2) KNN (v10 — verified exact): qq/pp strict; dot fma-ascending;
//    d = qq + (pp - 2*dot); ties lower-index-first.
// ---------------------------------------------------------------------------
__global__ void __launch_bounds__(256) knn_kernel(const float* __restrict__ xyz) {
    const int m = blockIdx.x;
    const int b = blockIdx.y;
    const float* p = xyz + (long)b * NN * 3;
    const int t = threadIdx.x;

    const int qi = g_fps[b * MM + m];
    const float qx = p[3 * qi + 0], qy = p[3 * qi + 1], qz = p[3 * qi + 2];
    const float qq = sq3(qx, qy, qz);

    float d[32];
#pragma unroll
    for (int j = 0; j < 32; j++) {
        int i = j * 256 + t;
        float x = p[3 * i + 0], y = p[3 * i + 1], z = p[3 * i + 2];
        float pp = sq3(x, y, z);
        float dot = __fmaf_rn(qz, z, __fmaf_rn(qy, y, __fmul_rn(qx, x)));
        d[j] = __fadd_rn(qq, __fsub_rn(pp, __fmul_rn(2.0f, dot)));
    }

    unsigned excl = 0u;
    float mv = d[0];
    int mi = t;
#pragma unroll
    for (int j = 1; j < 32; j++) {
        int i = j * 256 + t;
        if (d[j] < mv) { mv = d[j]; mi = i; }  // strict < : lower idx wins ties
    }

    __shared__ float s_v[8];
    __shared__ int   s_i[8];
    __shared__ int   s_b;
    const int lane = t & 31, w = t >> 5;
    const int out_base = (b * MM + m) * SS;

    for (int s = 0; s < SS; s++) {
        float bv = mv;
        int bi = mi;
#pragma unroll
        for (int o = 16; o > 0; o >>= 1) {
            float ov = __shfl_down_sync(0xffffffffu, bv, o);
            int   oi = __shfl_down_sync(0xffffffffu, bi, o);
            if (ov < bv || (ov == bv && oi < bi)) { bv = ov; bi = oi; }
        }
        if (lane == 0) { s_v[w] = bv; s_i[w] = bi; }
        __syncthreads();
        if (t == 0) {
            bv = s_v[0]; bi = s_i[0];
#pragma unroll
            for (int k = 1; k < 8; k++) {
                float ov = s_v[k]; int oi = s_i[k];
                if (ov < bv || (ov == bv && oi < bi)) { bv = ov; bi = oi; }
            }
            s_b = bi;
            g_nbr[out_base + s] = bi;
        }
        __syncthreads();
        int win = s_b;
        if ((win & 255) == t) {
            excl |= 1u << (win >> 8);
            mv = 3.4e38f;
            mi = 0x7fffffff;
#pragma unroll
            for (int j = 0; j < 32; j++) {
                if (!(excl & (1u << j))) {
                    int i = j * 256 + t;
                    if (d[j] < mv) { mv = d[j]; mi = i; }
                }
            }
        }
    }
}

// ---------------------------------------------------------------------------
// 3) group_xyz + new_xyz
// ---------------------------------------------------------------------------
__global__ void __launch_bounds__(256) gxyz_kernel(const float* __restrict__ xyz,
                                                   float* __restrict__ out) {
    int tid = blockIdx.x * 256 + threadIdx.x;
    if (tid >= BB * MM * SS) return;
    int s = tid & 31;
    int m = (tid >> 5) & (MM - 1);
    int b = tid >> 16;
    const float* p = xyz + (long)b * NN * 3;

    int i = g_nbr[tid];
    float* o = out + OFF_GXYZ + (long)tid * 3;
    o[0] = p[3 * i + 0];
    o[1] = p[3 * i + 1];
    o[2] = p[3 * i + 2];

    if (s == 0) {
        int q = g_fps[b * MM + m];
        float* o2 = out + OFF_NXYZ + (long)(b * MM + m) * 3;
        o2[0] = p[3 * q + 0];
        o2[1] = p[3 * q + 1];
        o2[2] = p[3 * q + 2];
    }
}

// ---------------------------------------------------------------------------
// 4) group_fts + new_fts_out
// ---------------------------------------------------------------------------
__global__ void __launch_bounds__(256) gfts_kernel(const float* __restrict__ fts,
                                                   float* __restrict__ out) {
    __shared__ float row[NN];
    __shared__ float ctr[512];

    const int r = blockIdx.x;       // 0..383
    const int chunk = blockIdx.y;   // 0..3
    const int b = r / (CC * DD);
    const int cd = r % (CC * DD);
    const int c = cd / DD;
    const int dd = cd % DD;
    const int t = threadIdx.x;

    const float* src = fts + ((long)(b * CC + c) * DD + dd) * NN;
#pragma unroll
    for (int k = 0; k < 8; k++) {
        int i = (k * 256 + t) * 4;
        *(float4*)&row[i] = *(const float4*)&src[i];
    }
    __syncthreads();

    const int m0 = chunk * 512;
#pragma unroll
    for (int k = 0; k < 2; k++) {
        int ml = k * 256 + t;
        ctr[ml] = row[g_fps[b * MM + m0 + ml]];
    }
    __syncthreads();

    float* o1 = out + OFF_GFTS + ((long)(b * 2 * CC + c) * DD + dd) * MM * SS;
    float* o2 = o1 + (long)CC * DD * MM * SS;
    const int* nb = g_nbr + (b * MM + m0) * SS;
    float* nfo1 = out + OFF_NFTS + ((long)(b * 2 * CC + c) * DD + dd) * MM + m0;
    float* nfo2 = nfo1 + (long)CC * DD * MM;

    for (int e = t; e < 512 * 8; e += 256) {
        int ml = e >> 3;
        int s4 = e & 7;
        int m = m0 + ml;
        int4 idx = *(const int4*)&nb[ml * SS + s4 * 4];
        float cv = ctr[ml];
        float4 v;
        v.x = __fsub_rn(row[idx.x], cv);
        v.y = __fsub_rn(row[idx.y], cv);
        v.z = __fsub_rn(row[idx.z], cv);
        v.w = __fsub_rn(row[idx.w], cv);
        long oo = (long)m * SS + s4 * 4;
        *(float4*)&o1[oo] = v;
        float4 cc4 = {cv, cv, cv, cv};
        *(float4*)&o2[oo] = cc4;
        if (s4 == 0) {
            nfo1[ml] = v.x;
            nfo2[ml] = cv;
        }
    }
}

// ---------------------------------------------------------------------------
extern "C" void kernel_launch(void* const* d_in, const int* in_sizes, int n_in,
                              void* d_out, int out_size) {
    const float* xyz = (const float*)d_in[0];
    const float* fts = (const float*)d_in[1];
    if (n_in >= 2 && in_sizes[0] != BB * NN * 3) {
        const float* tmp = xyz; xyz = fts; fts = tmp;
    }
    float* out = (float*)d_out;

    fps_kernel<<<BB, 256>>>(xyz);

    dim3 kg(MM, BB);
    knn_kernel<<<kg, 256>>>(xyz);

    gxyz_kernel<<<(BB * MM * SS + 255) / 256, 256>>>(xyz, out);

    dim3 gg(BB * CC * DD, 4);
    gfts_kernel<<<gg, 256>>>(fts, out);
}